// round 4
// baseline (speedup 1.0000x reference)
#include <cuda_runtime.h>
#include <cuda_bf16.h>

// BinaryLutLayer: out[i] = (float)(int8) round_half_even( luts_float[i][addr_i] + 0.5 )
// where addr_i = sum_b ((x[i][b] != 0) << b),  N = 16384 rows, 14 bits, LUT row = 16384.
//
// We recompute the int8 quantization from luts_float (d_in[1], guaranteed
// float32 on device) instead of touching d_in[2] (luts_int, dtype-ambiguous
// after the harness widened jnp.int8). rintf == jnp.round (round-half-even)
// on the identical float32 value, so this is bit-exact vs the reference.

#define NUM_BITS 14
#define LUT_SIZE 16384
#define N_OUT    16384
#define TPB      256

__global__ __launch_bounds__(TPB)
void binary_lut_kernel(const float* __restrict__ x,
                       const float* __restrict__ luts_float,
                       float* __restrict__ out)
{
    // Stage this block's slice of x (TPB rows x 14 floats) through shared
    // memory with fully coalesced global loads.
    __shared__ float sx[TPB * NUM_BITS];

    const int base = blockIdx.x * TPB;               // first row of this block
    const float* xb = x + (size_t)base * NUM_BITS;

    #pragma unroll
    for (int i = threadIdx.x; i < TPB * NUM_BITS; i += TPB)
        sx[i] = xb[i];
    __syncthreads();

    // Build the 14-bit address from binary inputs {0.0, 1.0}.
    const int t = threadIdx.x;
    int addr = 0;
    #pragma unroll
    for (int b = 0; b < NUM_BITS; b++)
        addr |= (sx[t * NUM_BITS + b] != 0.0f) ? (1 << b) : 0;

    const int row = base + t;
    // One scattered 4B gather per row (row stride = 64 KB in the float LUT).
    const float v = luts_float[(size_t)row * LUT_SIZE + addr];
    // round-half-even (== jnp.round), then int8 truncation, then float.
    out[row] = (float)(signed char)rintf(v + 0.5f);
}

extern "C" void kernel_launch(void* const* d_in, const int* in_sizes, int n_in,
                              void* d_out, int out_size)
{
    const float* x          = (const float*)d_in[0];
    const float* luts_float = (const float*)d_in[1];
    // d_in[2] (luts_int) deliberately unused: dtype after harness widening is
    // ambiguous; we reproduce its values exactly from luts_float instead.
    float* out = (float*)d_out;

    binary_lut_kernel<<<N_OUT / TPB, TPB>>>(x, luts_float, out);
}